// round 15
// baseline (speedup 1.0000x reference)
#include <cuda_runtime.h>
#include <stdint.h>

#define BATCH 64
#define T 2048
#define HID 256
#define FAST 64
#define SLOW 256
#define VOCAB 64
#define TLOOP (T - 3)

typedef unsigned long long u64;

__device__ __forceinline__ int warp_incl_scan(int x, int lane) {
    #pragma unroll
    for (int off = 1; off < 32; off <<= 1) {
        int t = __shfl_up_sync(0xffffffffu, x, off);
        if (lane >= off) x += t;
    }
    return x;
}

__device__ __forceinline__ float dot4(float4 a, float4 b) {
    return a.x * b.x + a.y * b.y + a.z * b.z + a.w * b.w;
}

#define DYN_SMEM (HID * VOCAB * 4)   // 64KB staged Wo

__global__ void __launch_bounds__(1024) fused_kernel(
    const int* __restrict__ seq,
    const float* __restrict__ emb,
    const float* __restrict__ Wg, const float* __restrict__ bg,
    const float* __restrict__ Wd, const float* __restrict__ bd,
    const float* __restrict__ Wq, const float* __restrict__ bq,
    const float* __restrict__ Wo, const float* __restrict__ bo,
    float* __restrict__ out)
{
    extern __shared__ float s_wo[];       // [HID*VOCAB], staged by B warps

    __shared__ __align__(16) float s_dem[VOCAB];
    __shared__ int s_vid[VOCAB];          // rank -> vid
    __shared__ unsigned s_am[2];
    __shared__ int s_ccnt[16];
    __shared__ int s_ha[VOCAB];           // hist by VID
    __shared__ int s_ht[VOCAB];           // window hist by VID
    __shared__ int s_mvid, s_m;
    __shared__ __align__(16) float s_qp[4][HID];   // 4 column-group partials
    __shared__ __align__(16) float s_q[HID];
    __shared__ float s_pv[VOCAB];         // score by vid
    __shared__ float s_wv[VOCAB];         // weight by VID
    __shared__ __align__(8) float2 s_ctxp2[1024];
    __shared__ float s_ctx[HID];
    __shared__ float s_lp[32 * VOCAB];

    const int b = blockIdx.x;
    const int tid = threadIdx.x;
    const int wid = tid >> 5, lane = tid & 31;

    if (tid < VOCAB) { s_ha[tid] = 0; s_ht[tid] = 0; }
    if (tid < 2) s_am[tid] = 0u;
    if (tid == 0) s_mvid = -1;

    if (tid < 512) {
        // ===================== pipeline A (16 warps) =====================
        const int4 tk = ((const int4*)(seq + b * T))[tid];

        const float bg0 = __ldg(bg);
        const float bd0 = __ldg(bd);
        const float4* emb4 = (const float4*)emb;
        const float4* wg4 = (const float4*)Wg;
        const float4 g0 = __ldg(wg4 + lane);
        const float4 g1 = __ldg(wg4 + 32 + lane);
        float4 d0, d1;      // Wd 4B-misaligned: scalar hoisted
        d0.x = __ldg(Wd + 4 * lane);     d0.y = __ldg(Wd + 4 * lane + 1);
        d0.z = __ldg(Wd + 4 * lane + 2); d0.w = __ldg(Wd + 4 * lane + 3);
        d1.x = __ldg(Wd + 128 + 4 * lane);     d1.y = __ldg(Wd + 128 + 4 * lane + 1);
        d1.z = __ldg(Wd + 128 + 4 * lane + 2); d1.w = __ldg(Wd + 128 + 4 * lane + 3);
        #pragma unroll
        for (int rr = 0; rr < 4; ++rr) {
            const int row = wid * 4 + rr;
            const float4 e0 = __ldg(emb4 + row * 64 + lane);
            const float4 e1 = __ldg(emb4 + row * 64 + 32 + lane);
            float ag = dot4(e0, g0) + dot4(e1, g1);
            float ad = dot4(e0, d0) + dot4(e1, d1);
            #pragma unroll
            for (int off = 16; off > 0; off >>= 1) {
                ag += __shfl_xor_sync(0xffffffffu, ag, off);
                ad += __shfl_xor_sync(0xffffffffu, ad, off);
            }
            if (lane == 0) {
                s_dem[row] = ad + bd0;
                float ws = 1.f / (1.f + __expf(-(ag + bg0)));
                if (ws >= 0.4f) atomicOr(&s_am[row >> 5], 1u << (row & 31));
            }
        }
        asm volatile("bar.sync 1, 512;" ::: "memory");

        // rank -> vid (needed only by the warp-0 softmax stage)
        if (tid < VOCAB) {
            const float dv = s_dem[tid];
            const float4* dem4 = (const float4*)s_dem;
            int rank = 0;
            #pragma unroll
            for (int u4 = 0; u4 < 16; ++u4) {
                const float4 d = dem4[u4];
                const int u = 4 * u4;
                rank += (d.x < dv || (d.x == dv && u + 0 < tid));
                rank += (d.y < dv || (d.y == dv && u + 1 < tid));
                rank += (d.z < dv || (d.z == dv && u + 2 < tid));
                rank += (d.w < dv || (d.w == dv && u + 3 < tid));
            }
            s_vid[rank] = tid;
        }

        const u64 act = (u64)s_am[0] | ((u64)s_am[1] << 32);

        // pass 1: 4 register tokens; vid-indexed histogram + warp counts
        const int gt0 = 4 * tid;
        const bool a0 = (gt0 + 0 < TLOOP) && (((act >> tk.x) & 1ull) != 0ull);
        const bool a1 = (gt0 + 1 < TLOOP) && (((act >> tk.y) & 1ull) != 0ull);
        const bool a2 = (gt0 + 2 < TLOOP) && (((act >> tk.z) & 1ull) != 0ull);
        const bool a3 = (gt0 + 3 < TLOOP) && (((act >> tk.w) & 1ull) != 0ull);
        const int pc = (int)a0 + (int)a1 + (int)a2 + (int)a3;
        const int sc = warp_incl_scan(pc, lane);
        if (lane == 31) s_ccnt[wid] = sc;
        if (a0) atomicAdd(&s_ha[tk.x], 1);
        if (a1) atomicAdd(&s_ha[tk.y], 1);
        if (a2) atomicAdd(&s_ha[tk.z], 1);
        if (a3) atomicAdd(&s_ha[tk.w], 1);
        asm volatile("bar.sync 1, 512;" ::: "memory");

        // local prefix over the 16 warp counts (no block scan, no barrier)
        int lo = 0, m = 0;
        #pragma unroll
        for (int w = 0; w < 16; ++w) {
            const int c = s_ccnt[w];
            lo += (w < wid) ? c : 0;
            m += c;
        }
        if (tid == 0) s_m = m;

        if (tid < SLOW) {
            const int ne_ = (m > FAST) ? (m - FAST) : 0;
            const int sc_ = (ne_ < SLOW) ? ne_ : SLOW;
            out[BATCH * VOCAB + b * SLOW + tid] = (tid < sc_) ? 1.f : 0.f;
        }
        // window pass
        const int wlo = m - 256;
        const int wtot = s_ccnt[wid];
        if (lo + wtot >= wlo) {
            int yi = lo + (sc - pc);
            if (a0) { ++yi; if (yi >= wlo && yi <= m - 1) atomicAdd(&s_ht[tk.x], 1);
                      if (yi == m) s_mvid = tk.x; }
            if (a1) { ++yi; if (yi >= wlo && yi <= m - 1) atomicAdd(&s_ht[tk.y], 1);
                      if (yi == m) s_mvid = tk.y; }
            if (a2) { ++yi; if (yi >= wlo && yi <= m - 1) atomicAdd(&s_ht[tk.z], 1);
                      if (yi == m) s_mvid = tk.z; }
            if (a3) { ++yi; if (yi >= wlo && yi <= m - 1) atomicAdd(&s_ht[tk.w], 1);
                      if (yi == m) s_mvid = tk.w; }
        }
    } else {
        // ===================== pipeline B (16 warps) =====================
        const int bw = wid - 16;            // 0..15
        const int grpB = bw >> 2;           // column group 0..3 (64 cols)
        const int sub = bw & 3;             // row quarter 0..3 (64 rows)
        const int lv = __ldg(seq + b * T + T - 1);
        const float ev0 = __ldg(emb + lv * HID + sub * 64 + lane);
        const float ev1 = __ldg(emb + lv * HID + sub * 64 + 32 + lane);

        // q matvec: warp covers 64 rows x 64 cols (1 float2/lane/row)
        const float2* Wq2 = (const float2*)Wq;    // 8B-aligned
        float2 qa = make_float2(0.f, 0.f);
        #pragma unroll 8
        for (int rr = 0; rr < 32; ++rr) {
            const int h0 = sub * 64 + rr;
            const int h1 = h0 + 32;
            const float e0 = __shfl_sync(0xffffffffu, ev0, rr);
            const float e1 = __shfl_sync(0xffffffffu, ev1, rr);
            const float2 v0 = Wq2[h0 * 128 + grpB * 32 + lane];
            const float2 v1 = Wq2[h1 * 128 + grpB * 32 + lane];
            qa.x += e0 * v0.x + e1 * v1.x;
            qa.y += e0 * v0.y + e1 * v1.y;
        }
        ((float2*)(s_qp[sub]))[grpB * 32 + lane] = qa;
        asm volatile("bar.sync 2, 512;" ::: "memory");

        {
            const int j = tid - 512;
            if (j < HID) {
                float acc = __ldg(bq + j) + s_qp[0][j] + s_qp[1][j] +
                            s_qp[2][j] + s_qp[3][j];
                s_q[j] = acc;
            }
        }
        asm volatile("bar.sync 2, 512;" ::: "memory");

        // p[v] = emb[v] . q  (float4 emb + LDS.128 q)
        const float4* emb4 = (const float4*)emb;
        const float4* q4 = (const float4*)s_q;
        const float4 qra = q4[lane];
        const float4 qrb = q4[32 + lane];
        #pragma unroll
        for (int rr = 0; rr < 4; ++rr) {
            const int v = bw * 4 + rr;
            const float4 e0 = __ldg(emb4 + v * 64 + lane);
            const float4 e1 = __ldg(emb4 + v * 64 + 32 + lane);
            float acc = dot4(e0, qra) + dot4(e1, qrb);
            #pragma unroll
            for (int off = 16; off > 0; off >>= 1)
                acc += __shfl_xor_sync(0xffffffffu, acc, off);
            if (lane == 0) s_pv[v] = acc;
        }

        // shadow prefetch: stage Wo (64KB) into smem for the logits phase
        {
            const int j = tid - 512;            // 0..511
            const float2* Wo2 = (const float2*)Wo;   // 8B-aligned
            float2* swo2 = (float2*)s_wo;
            #pragma unroll
            for (int k = 0; k < 16; ++k)
                swo2[j + 512 * k] = __ldg(Wo2 + j + 512 * k);
        }
    }
    __syncthreads();

    // ============ warp 0: counts + softmax -> weights by VID ============
    if (wid == 0) {
        const int m = s_m;
        const int mvid = s_mvid;
        const int ne = (m > FAST) ? (m - FAST) : 0;
        const int k1 = ne;
        const int k2 = (ne > SLOW) ? (ne - SLOW) : 0;
        const int r0 = 2 * lane, r1 = 2 * lane + 1;
        const int v0i = s_vid[r0], v1i = s_vid[r1];

        int h1a = s_ha[v0i] - (v0i == mvid ? 1 : 0);
        int h1b = s_ha[v1i] - (v1i == mvid ? 1 : 0);
        int h2a = h1a - s_ht[v0i];
        int h2b = h1b - s_ht[v1i];

        int s1 = warp_incl_scan(h1a + h1b, lane);
        int s2 = warp_incl_scan(h2a + h2b, lane);
        int c1a = s1 - h1a - h1b, c1b = c1a + h1a;
        int c2a = s2 - h2a - h2b, c2b = c2a + h2a;

        int e1a = k1 - c1a; e1a = e1a < 0 ? 0 : e1a; e1a = e1a > h1a ? h1a : e1a;
        int e1b = k1 - c1b; e1b = e1b < 0 ? 0 : e1b; e1b = e1b > h1b ? h1b : e1b;
        int e2a = k2 - c2a; e2a = e2a < 0 ? 0 : e2a; e2a = e2a > h2a ? h2a : e2a;
        int e2b = k2 - c2b; e2b = e2b < 0 ? 0 : e2b; e2b = e2b > h2b ? h2b : e2b;

        int ct0 = (h1a - e1a + (v0i == mvid ? 1 : 0)) + (e1a - e2a);
        int ct1 = (h1b - e1b + (v1i == mvid ? 1 : 0)) + (e1b - e2b);

        const float p0 = s_pv[v0i];
        const float p1 = s_pv[v1i];

        float v = fmaxf(ct0 > 0 ? p0 : -3.402823466e38f,
                        ct1 > 0 ? p1 : -3.402823466e38f);
        #pragma unroll
        for (int off = 16; off > 0; off >>= 1)
            v = fmaxf(v, __shfl_xor_sync(0xffffffffu, v, off));
        const float mx = v;

        float e0 = (ct0 > 0) ? (float)ct0 * __expf(p0 - mx) : 0.f;
        float e1 = (ct1 > 0) ? (float)ct1 * __expf(p1 - mx) : 0.f;
        float sm = e0 + e1;
        #pragma unroll
        for (int off = 16; off > 0; off >>= 1)
            sm += __shfl_xor_sync(0xffffffffu, sm, off);
        const float inv = (sm > 0.f) ? (1.f / sm) : 0.f;
        s_wv[v0i] = e0 * inv;     // weight indexed by VID
        s_wv[v1i] = e1 * inv;
    }
    __syncthreads();

    // ctx: vid-affine loop; h-pair = tid&127, grp = tid>>7
    {
        const int h2 = tid & 127;
        const int grp = tid >> 7;
        const float2* emb2 = (const float2*)emb;
        float2 c = make_float2(0.f, 0.f);
        #pragma unroll
        for (int rr = 0; rr < 8; ++rr) {
            const int v = grp * 8 + rr;          // affine vid
            const float w = s_wv[v];
            const float2 e = __ldg(emb2 + v * 128 + h2);
            c.x += w * e.x;
            c.y += w * e.y;
        }
        s_ctxp2[tid] = c;
    }
    __syncthreads();
    if (tid < 128) {
        float2 acc = make_float2(0.f, 0.f);
        #pragma unroll
        for (int g = 0; g < 8; ++g) {
            const float2 c = s_ctxp2[g * 128 + tid];
            acc.x += c.x;
            acc.y += c.y;
        }
        s_ctx[2 * tid] = acc.x;
        s_ctx[2 * tid + 1] = acc.y;
    }
    __syncthreads();

    // logits: 32 warps x 8 Wo rows each, from staged smem
    {
        const float2* swo2 = (const float2*)s_wo;
        float2 acc = make_float2(0.f, 0.f);
        #pragma unroll
        for (int it = 0; it < 8; ++it) {
            const int row = wid * 8 + it;
            const float c = s_ctx[row];
            const float2 v = swo2[row * 32 + lane];
            acc.x += c * v.x;
            acc.y += c * v.y;
        }
        ((float2*)(s_lp + wid * VOCAB))[lane] = acc;
    }
    __syncthreads();
    if (tid < VOCAB) {
        float acc = __ldg(bo + tid);
        #pragma unroll
        for (int w = 0; w < 32; ++w) acc += s_lp[w * VOCAB + tid];
        out[b * VOCAB + tid] = acc;
    }
}

extern "C" void kernel_launch(void* const* d_in, const int* in_sizes, int n_in,
                              void* d_out, int out_size) {
    const int*   seq = (const int*)d_in[0];
    const float* emb = (const float*)d_in[1];
    const float* Wg  = (const float*)d_in[2];
    const float* bg  = (const float*)d_in[3];
    const float* Wd  = (const float*)d_in[4];
    const float* bd  = (const float*)d_in[5];
    const float* Wq  = (const float*)d_in[6];
    const float* bq  = (const float*)d_in[7];
    const float* Wo  = (const float*)d_in[8];
    const float* bo  = (const float*)d_in[9];
    float* out = (float*)d_out;

    static int attr_set = 0;
    if (!attr_set) {
        cudaFuncSetAttribute(fused_kernel,
                             cudaFuncAttributeMaxDynamicSharedMemorySize,
                             DYN_SMEM);
        attr_set = 1;
    }
    fused_kernel<<<BATCH, 1024, DYN_SMEM>>>(seq, emb, Wg, bg, Wd, bd,
                                            Wq, bq, Wo, bo, out);
}

// round 16
// speedup vs baseline: 1.6000x; 1.6000x over previous
#include <cuda_runtime.h>
#include <stdint.h>

#define BATCH 64
#define T 2048
#define HID 256
#define FAST 64
#define SLOW 256
#define VOCAB 64
#define TLOOP (T - 3)

typedef unsigned long long u64;

__device__ __forceinline__ int warp_incl_scan(int x, int lane) {
    #pragma unroll
    for (int off = 1; off < 32; off <<= 1) {
        int t = __shfl_up_sync(0xffffffffu, x, off);
        if (lane >= off) x += t;
    }
    return x;
}

__device__ __forceinline__ float dot4(float4 a, float4 b) {
    return a.x * b.x + a.y * b.y + a.z * b.z + a.w * b.w;
}

__global__ void __launch_bounds__(1024) fused_kernel(
    const int* __restrict__ seq,
    const float* __restrict__ emb,
    const float* __restrict__ Wg, const float* __restrict__ bg,
    const float* __restrict__ Wd, const float* __restrict__ bd,
    const float* __restrict__ Wq, const float* __restrict__ bq,
    const float* __restrict__ Wo, const float* __restrict__ bo,
    float* __restrict__ out)
{
    __shared__ __align__(16) float s_dem[VOCAB];
    __shared__ int s_vid[VOCAB];          // rank -> vid
    __shared__ unsigned s_am[2];
    __shared__ int s_ccnt[16];
    __shared__ int s_cpre[16];
    __shared__ int s_ha[VOCAB];           // hist by VID
    __shared__ int s_ht[VOCAB];           // window hist by VID
    __shared__ int s_mvid, s_m;
    __shared__ __align__(16) float s_qp[16][HID];
    __shared__ __align__(16) float s_q[HID];
    __shared__ float s_pv[VOCAB];         // score by vid
    __shared__ float s_w[VOCAB];          // weight by rank
    __shared__ __align__(8) float2 s_ctxp2[1024];
    __shared__ float s_ctx[HID];
    __shared__ float s_lp[32 * VOCAB];

    const int b = blockIdx.x;
    const int tid = threadIdx.x;
    const int wid = tid >> 5, lane = tid & 31;

    if (tid < VOCAB) { s_ha[tid] = 0; s_ht[tid] = 0; }
    if (tid < 2) s_am[tid] = 0u;
    if (tid == 0) s_mvid = -1;

    if (tid < 512) {
        // ===================== pipeline A (16 warps) =====================
        const int4 tk = ((const int4*)(seq + b * T))[tid];

        // gates/dem: 4 rows per warp; vectorized loads
        const float bg0 = __ldg(bg);
        const float bd0 = __ldg(bd);
        const float4* emb4 = (const float4*)emb;
        const float4* wg4 = (const float4*)Wg;
        const float4 g0 = __ldg(wg4 + lane);
        const float4 g1 = __ldg(wg4 + 32 + lane);
        float4 d0, d1;      // Wd is 4B-misaligned: scalar loads, hoisted
        d0.x = __ldg(Wd + 4 * lane);     d0.y = __ldg(Wd + 4 * lane + 1);
        d0.z = __ldg(Wd + 4 * lane + 2); d0.w = __ldg(Wd + 4 * lane + 3);
        d1.x = __ldg(Wd + 128 + 4 * lane);     d1.y = __ldg(Wd + 128 + 4 * lane + 1);
        d1.z = __ldg(Wd + 128 + 4 * lane + 2); d1.w = __ldg(Wd + 128 + 4 * lane + 3);
        #pragma unroll
        for (int rr = 0; rr < 4; ++rr) {
            const int row = wid * 4 + rr;
            const float4 e0 = __ldg(emb4 + row * 64 + lane);
            const float4 e1 = __ldg(emb4 + row * 64 + 32 + lane);
            float ag = dot4(e0, g0) + dot4(e1, g1);
            float ad = dot4(e0, d0) + dot4(e1, d1);
            #pragma unroll
            for (int off = 16; off > 0; off >>= 1) {
                ag += __shfl_xor_sync(0xffffffffu, ag, off);
                ad += __shfl_xor_sync(0xffffffffu, ad, off);
            }
            if (lane == 0) {
                s_dem[row] = ad + bd0;
                float ws = 1.f / (1.f + __expf(-(ag + bg0)));
                if (ws >= 0.4f) atomicOr(&s_am[row >> 5], 1u << (row & 31));
            }
        }
        asm volatile("bar.sync 1, 512;" ::: "memory");

        // rank -> vid (float4 LDS over s_dem)
        if (tid < VOCAB) {
            const float dv = s_dem[tid];
            const float4* dem4 = (const float4*)s_dem;
            int rank = 0;
            #pragma unroll
            for (int u4 = 0; u4 < 16; ++u4) {
                const float4 d = dem4[u4];
                const int u = 4 * u4;
                rank += (d.x < dv || (d.x == dv && u + 0 < tid));
                rank += (d.y < dv || (d.y == dv && u + 1 < tid));
                rank += (d.z < dv || (d.z == dv && u + 2 < tid));
                rank += (d.w < dv || (d.w == dv && u + 3 < tid));
            }
            s_vid[rank] = tid;
        }

        const u64 act = (u64)s_am[0] | ((u64)s_am[1] << 32);

        // pass 1: activity of 4 register tokens; vid-indexed histogram
        const int gt0 = 4 * tid;
        const bool a0 = (gt0 + 0 < TLOOP) && (((act >> tk.x) & 1ull) != 0ull);
        const bool a1 = (gt0 + 1 < TLOOP) && (((act >> tk.y) & 1ull) != 0ull);
        const bool a2 = (gt0 + 2 < TLOOP) && (((act >> tk.z) & 1ull) != 0ull);
        const bool a3 = (gt0 + 3 < TLOOP) && (((act >> tk.w) & 1ull) != 0ull);
        const int pc = (int)a0 + (int)a1 + (int)a2 + (int)a3;
        const int sc = warp_incl_scan(pc, lane);
        if (lane == 31) s_ccnt[wid] = sc;
        if (a0) atomicAdd(&s_ha[tk.x], 1);
        if (a1) atomicAdd(&s_ha[tk.y], 1);
        if (a2) atomicAdd(&s_ha[tk.z], 1);
        if (a3) atomicAdd(&s_ha[tk.w], 1);
        asm volatile("bar.sync 1, 512;" ::: "memory");

        if (wid == 0) {
            int v = (lane < 16) ? s_ccnt[lane] : 0;
            int s = warp_incl_scan(v, lane);
            if (lane < 16) s_cpre[lane] = s - v;
            if (lane == 15) s_m = s;
        }
        asm volatile("bar.sync 1, 512;" ::: "memory");

        const int m = s_m;
        if (tid < SLOW) {
            const int ne_ = (m > FAST) ? (m - FAST) : 0;
            const int sc_ = (ne_ < SLOW) ? ne_ : SLOW;
            out[BATCH * VOCAB + b * SLOW + tid] = (tid < sc_) ? 1.f : 0.f;
        }
        // window pass on register tokens
        const int wlo = m - 256;
        const int lo = s_cpre[wid];
        const int wtot = s_ccnt[wid];
        if (lo + wtot >= wlo) {
            int yi = lo + (sc - pc);
            if (a0) { ++yi; if (yi >= wlo && yi <= m - 1) atomicAdd(&s_ht[tk.x], 1);
                      if (yi == m) s_mvid = tk.x; }
            if (a1) { ++yi; if (yi >= wlo && yi <= m - 1) atomicAdd(&s_ht[tk.y], 1);
                      if (yi == m) s_mvid = tk.y; }
            if (a2) { ++yi; if (yi >= wlo && yi <= m - 1) atomicAdd(&s_ht[tk.z], 1);
                      if (yi == m) s_mvid = tk.z; }
            if (a3) { ++yi; if (yi >= wlo && yi <= m - 1) atomicAdd(&s_ht[tk.w], 1);
                      if (yi == m) s_mvid = tk.w; }
        }
    } else {
        // ===================== pipeline B (16 warps) =====================
        const int bw = wid - 16;            // 0..15
        const int lv = __ldg(seq + b * T + T - 1);
        const float ev = (lane < 16)
            ? __ldg(emb + lv * HID + bw * 16 + lane) : 0.f;

        // q matvec: warp bw owns 16 rows; float2 (Wq is 8B-aligned)
        const float2* Wq2 = (const float2*)Wq;
        float2 q0 = make_float2(0.f, 0.f);
        float2 q1 = make_float2(0.f, 0.f);
        float2 q2 = make_float2(0.f, 0.f);
        float2 q3 = make_float2(0.f, 0.f);
        #pragma unroll
        for (int rr = 0; rr < 16; ++rr) {
            const int h = bw * 16 + rr;
            const float e = __shfl_sync(0xffffffffu, ev, rr);
            const float2 v0 = Wq2[h * 128 + lane];
            const float2 v1 = Wq2[h * 128 + 32 + lane];
            const float2 v2 = Wq2[h * 128 + 64 + lane];
            const float2 v3 = Wq2[h * 128 + 96 + lane];
            q0.x += e * v0.x; q0.y += e * v0.y;
            q1.x += e * v1.x; q1.y += e * v1.y;
            q2.x += e * v2.x; q2.y += e * v2.y;
            q3.x += e * v3.x; q3.y += e * v3.y;
        }
        {
            float2* qp2 = (float2*)(s_qp[bw]);
            qp2[lane] = q0;
            qp2[32 + lane] = q1;
            qp2[64 + lane] = q2;
            qp2[96 + lane] = q3;
        }
        asm volatile("bar.sync 2, 512;" ::: "memory");

        {
            const int j = tid - 512;
            if (j < HID) {
                float acc = __ldg(bq + j);
                #pragma unroll
                for (int w = 0; w < 16; ++w) acc += s_qp[w][j];
                s_q[j] = acc;
            }
        }
        asm volatile("bar.sync 2, 512;" ::: "memory");

        // p[v] = emb[v] . q  (float4 emb + LDS.128 q, q hoisted)
        const float4* emb4 = (const float4*)emb;
        const float4* q4 = (const float4*)s_q;
        const float4 qa = q4[lane];
        const float4 qb = q4[32 + lane];
        #pragma unroll
        for (int rr = 0; rr < 4; ++rr) {
            const int v = bw * 4 + rr;
            const float4 e0 = __ldg(emb4 + v * 64 + lane);
            const float4 e1 = __ldg(emb4 + v * 64 + 32 + lane);
            float acc = dot4(e0, qa) + dot4(e1, qb);
            #pragma unroll
            for (int off = 16; off > 0; off >>= 1)
                acc += __shfl_xor_sync(0xffffffffu, acc, off);
            if (lane == 0) s_pv[v] = acc;
        }
    }
    __syncthreads();

    // ============ warp 0: counts + softmax (vid-mapped) ============
    if (wid == 0) {
        const int m = s_m;
        const int mvid = s_mvid;
        const int ne = (m > FAST) ? (m - FAST) : 0;
        const int k1 = ne;
        const int k2 = (ne > SLOW) ? (ne - SLOW) : 0;
        const int r0 = 2 * lane, r1 = 2 * lane + 1;
        const int v0i = s_vid[r0], v1i = s_vid[r1];

        int h1a = s_ha[v0i] - (v0i == mvid ? 1 : 0);
        int h1b = s_ha[v1i] - (v1i == mvid ? 1 : 0);
        int h2a = h1a - s_ht[v0i];
        int h2b = h1b - s_ht[v1i];

        int s1 = warp_incl_scan(h1a + h1b, lane);
        int s2 = warp_incl_scan(h2a + h2b, lane);
        int c1a = s1 - h1a - h1b, c1b = c1a + h1a;
        int c2a = s2 - h2a - h2b, c2b = c2a + h2a;

        int e1a = k1 - c1a; e1a = e1a < 0 ? 0 : e1a; e1a = e1a > h1a ? h1a : e1a;
        int e1b = k1 - c1b; e1b = e1b < 0 ? 0 : e1b; e1b = e1b > h1b ? h1b : e1b;
        int e2a = k2 - c2a; e2a = e2a < 0 ? 0 : e2a; e2a = e2a > h2a ? h2a : e2a;
        int e2b = k2 - c2b; e2b = e2b < 0 ? 0 : e2b; e2b = e2b > h2b ? h2b : e2b;

        int ct0 = (h1a - e1a + (v0i == mvid ? 1 : 0)) + (e1a - e2a);
        int ct1 = (h1b - e1b + (v1i == mvid ? 1 : 0)) + (e1b - e2b);

        float p0 = s_pv[v0i];
        float p1 = s_pv[v1i];

        float v = fmaxf(ct0 > 0 ? p0 : -3.402823466e38f,
                        ct1 > 0 ? p1 : -3.402823466e38f);
        #pragma unroll
        for (int off = 16; off > 0; off >>= 1)
            v = fmaxf(v, __shfl_xor_sync(0xffffffffu, v, off));
        const float mx = v;

        float e0 = (ct0 > 0) ? (float)ct0 * __expf(p0 - mx) : 0.f;
        float e1 = (ct1 > 0) ? (float)ct1 * __expf(p1 - mx) : 0.f;
        float sm = e0 + e1;
        #pragma unroll
        for (int off = 16; off > 0; off >>= 1)
            sm += __shfl_xor_sync(0xffffffffu, sm, off);
        const float inv = (sm > 0.f) ? (1.f / sm) : 0.f;
        s_w[r0] = e0 * inv;
        s_w[r1] = e1 * inv;
    }
    __syncthreads();

    // ctx: 1024 threads, h-pair = tid&127, group = tid>>7 (8 ranks each)
    {
        const int h2 = tid & 127;
        const int grp = tid >> 7;
        const float2* emb2 = (const float2*)emb;
        float2 c = make_float2(0.f, 0.f);
        #pragma unroll
        for (int rr = 0; rr < 8; ++rr) {
            const int r = grp * 8 + rr;
            const float w = s_w[r];
            const float2 e = __ldg(emb2 + s_vid[r] * 128 + h2);
            c.x += w * e.x;
            c.y += w * e.y;
        }
        s_ctxp2[tid] = c;
    }
    __syncthreads();
    if (tid < 128) {
        float2 acc = make_float2(0.f, 0.f);
        #pragma unroll
        for (int g = 0; g < 8; ++g) {
            const float2 c = s_ctxp2[g * 128 + tid];
            acc.x += c.x;
            acc.y += c.y;
        }
        s_ctx[2 * tid] = acc.x;
        s_ctx[2 * tid + 1] = acc.y;
    }
    __syncthreads();

    // logits: 32 warps x 8 Wo rows each, float2 (Wo 8B-aligned)
    {
        const float2* Wo2 = (const float2*)Wo;
        float2 acc = make_float2(0.f, 0.f);
        #pragma unroll
        for (int it = 0; it < 8; ++it) {
            const int row = wid * 8 + it;
            const float c = s_ctx[row];
            const float2 v = Wo2[row * 32 + lane];
            acc.x += c * v.x;
            acc.y += c * v.y;
        }
        ((float2*)(s_lp + wid * VOCAB))[lane] = acc;
    }
    __syncthreads();
    if (tid < VOCAB) {
        float acc = __ldg(bo + tid);
        #pragma unroll
        for (int w = 0; w < 32; ++w) acc += s_lp[w * VOCAB + tid];
        out[b * VOCAB + tid] = acc;
    }
}

extern "C" void kernel_launch(void* const* d_in, const int* in_sizes, int n_in,
                              void* d_out, int out_size) {
    const int*   seq = (const int*)d_in[0];
    const float* emb = (const float*)d_in[1];
    const float* Wg  = (const float*)d_in[2];
    const float* bg  = (const float*)d_in[3];
    const float* Wd  = (const float*)d_in[4];
    const float* bd  = (const float*)d_in[5];
    const float* Wq  = (const float*)d_in[6];
    const float* bq  = (const float*)d_in[7];
    const float* Wo  = (const float*)d_in[8];
    const float* bo  = (const float*)d_in[9];
    float* out = (float*)d_out;

    fused_kernel<<<BATCH, 1024>>>(seq, emb, Wg, bg, Wd, bd, Wq, bq, Wo, bo, out);
}